// round 1
// baseline (speedup 1.0000x reference)
#include <cuda_runtime.h>

// AtomicLinear: out[b,o] = sum_i x[b,i] * W[o,i] + bias[o]
// M=4096 (batch), N=2048 (out features), K=2048 (in features). All fp32.
// Both x and W are K-major -> this is A @ B^T with contiguous K on both sides.

namespace {

constexpr int Mdim = 4096;
constexpr int Ndim = 2048;
constexpr int Kdim = 2048;

constexpr int BM = 128;
constexpr int BN = 128;
constexpr int BK = 16;

// 256 threads, each computes an 8x8 microtile split as 2x2 quadrants of 4x4:
// rows {ty*4 .. +3, 64+ty*4 .. +3}, cols {tx*4 .. +3, 64+tx*4 .. +3}.
// The *4 / +64 split keeps fragment LDS.128 conflict-free (stride-4-word
// pattern covers all 32 banks per 8-lane phase; stride-8 would 2-way conflict).

__global__ __launch_bounds__(256, 2)
void linear_kernel(const float* __restrict__ A,   // x  [M, K]
                   const float* __restrict__ W,   // w  [N, K]
                   const float* __restrict__ bias,// [N]
                   float* __restrict__ C)         // out [M, N]
{
    __shared__ float As[BK][BM + 4];   // +4 pad: reduce STS transpose conflicts
    __shared__ float Bs[BK][BN + 4];

    const int tid = threadIdx.x;
    const int tx  = tid & 15;          // 0..15 -> N direction
    const int ty  = tid >> 4;          // 0..15 -> M direction
    const int bm  = blockIdx.y * BM;
    const int bn  = blockIdx.x * BN;

    // Global-load mapping: 2 float4 per thread per operand tile.
    // Tile is 128 rows x 16 k. idx -> (row = idx/4, kchunk = (idx%4)*4).
    const int r0 = tid >> 2;           // rows 0..63 (second chunk = +64)
    const int c0 = (tid & 3) * 4;      // k offset 0,4,8,12

    const float* Ap = A + (size_t)(bm + r0) * Kdim + c0;
    const float* Wp = W + (size_t)(bn + r0) * Kdim + c0;

    // Prefetch registers for the K-tile currently being staged.
    float4 av0 = *(const float4*)(Ap);
    float4 av1 = *(const float4*)(Ap + (size_t)64 * Kdim);
    float4 bv0 = *(const float4*)(Wp);
    float4 bv1 = *(const float4*)(Wp + (size_t)64 * Kdim);

    float acc[8][8];
    #pragma unroll
    for (int i = 0; i < 8; i++)
        #pragma unroll
        for (int j = 0; j < 8; j++) acc[i][j] = 0.0f;

    const int row0 = ty * 4;
    const int col0 = tx * 4;

    for (int kt = 0; kt < Kdim; kt += BK) {
        __syncthreads();   // previous iteration done reading smem

        // Stage registers -> smem, transposed so inner loop reads contiguous.
        As[c0 + 0][r0]      = av0.x;
        As[c0 + 1][r0]      = av0.y;
        As[c0 + 2][r0]      = av0.z;
        As[c0 + 3][r0]      = av0.w;
        As[c0 + 0][r0 + 64] = av1.x;
        As[c0 + 1][r0 + 64] = av1.y;
        As[c0 + 2][r0 + 64] = av1.z;
        As[c0 + 3][r0 + 64] = av1.w;

        Bs[c0 + 0][r0]      = bv0.x;
        Bs[c0 + 1][r0]      = bv0.y;
        Bs[c0 + 2][r0]      = bv0.z;
        Bs[c0 + 3][r0]      = bv0.w;
        Bs[c0 + 0][r0 + 64] = bv1.x;
        Bs[c0 + 1][r0 + 64] = bv1.y;
        Bs[c0 + 2][r0 + 64] = bv1.z;
        Bs[c0 + 3][r0 + 64] = bv1.w;

        __syncthreads();

        // Prefetch next K-tile (overlaps LDG latency with the FFMA loop below).
        if (kt + BK < Kdim) {
            const int ko = kt + BK;
            av0 = *(const float4*)(Ap + ko);
            av1 = *(const float4*)(Ap + (size_t)64 * Kdim + ko);
            bv0 = *(const float4*)(Wp + ko);
            bv1 = *(const float4*)(Wp + (size_t)64 * Kdim + ko);
        }

        #pragma unroll
        for (int k = 0; k < BK; k++) {
            float a[8], b[8];
            #pragma unroll
            for (int i = 0; i < 4; i++) {
                a[i]     = As[k][row0 + i];
                a[4 + i] = As[k][row0 + 64 + i];
                b[i]     = Bs[k][col0 + i];
                b[4 + i] = Bs[k][col0 + 64 + i];
            }
            #pragma unroll
            for (int i = 0; i < 8; i++)
                #pragma unroll
                for (int j = 0; j < 8; j++)
                    acc[i][j] = fmaf(a[i], b[j], acc[i][j]);
        }
    }

    // Epilogue: add bias, vectorized stores (half-warp writes 256B contiguous).
    float bv[8];
    #pragma unroll
    for (int j = 0; j < 4; j++) {
        bv[j]     = bias[bn + col0 + j];
        bv[4 + j] = bias[bn + col0 + 64 + j];
    }

    #pragma unroll
    for (int i = 0; i < 8; i++) {
        const int r = bm + ((i < 4) ? (row0 + i) : (row0 + 64 + (i - 4)));
        float* crow = C + (size_t)r * Ndim + bn;

        float4 v0;
        v0.x = acc[i][0] + bv[0];
        v0.y = acc[i][1] + bv[1];
        v0.z = acc[i][2] + bv[2];
        v0.w = acc[i][3] + bv[3];
        *(float4*)(crow + col0) = v0;

        float4 v1;
        v1.x = acc[i][4] + bv[4];
        v1.y = acc[i][5] + bv[5];
        v1.z = acc[i][6] + bv[6];
        v1.w = acc[i][7] + bv[7];
        *(float4*)(crow + col0 + 64) = v1;
    }
}

} // namespace

extern "C" void kernel_launch(void* const* d_in, const int* in_sizes, int n_in,
                              void* d_out, int out_size)
{
    const float* x    = (const float*)d_in[0];
    const float* w    = (const float*)d_in[1];
    const float* bias = (const float*)d_in[2];
    float* out        = (float*)d_out;

    dim3 grid(Ndim / BN, Mdim / BM);   // (16, 32) = 512 CTAs
    linear_kernel<<<grid, 256>>>(x, w, bias, out);
}

// round 3
// speedup vs baseline: 3.0659x; 3.0659x over previous
#include <cuda_runtime.h>
#include <cstdint>

// out[4096,2048] = x[4096,2048] @ W[2048,2048]^T + bias   (fp32 in/out)
// tf32 mma.sync.m16n8k8 GEMM (family-portable PTX; tcgen05.ld is rejected by
// the harness's compute_103 PTX target). 5-stage cp.async pipeline,
// SW128-swizzled smem, ldmatrix-b16 fragment loads, cvt.rna tf32 rounding.

namespace {

constexpr int Mdim = 4096;
constexpr int Ndim = 2048;
constexpr int Kdim = 2048;

constexpr int BM = 128;
constexpr int BN = 128;
constexpr int BK = 32;                    // 32 f32 = 128 B rows (SW128 atom)
constexpr int KT = Kdim / BK;             // 64 k-tiles
constexpr int STAGES = 5;

constexpr uint32_t A_BYTES = BM * BK * 4;            // 16384
constexpr uint32_t B_BYTES = BN * BK * 4;            // 16384
constexpr uint32_t STAGE_BYTES = A_BYTES + B_BYTES;  // 32768
constexpr uint32_t SMEM_TOTAL = STAGES * STAGE_BYTES; // 163840

constexpr int THREADS = 256;

__device__ __forceinline__ uint32_t smem_u32(const void* p) {
    return (uint32_t)__cvta_generic_to_shared(p);
}
__device__ __forceinline__ uint32_t sw128(uint32_t off) {
    return off ^ ((off >> 3) & 0x70);
}
__device__ __forceinline__ void cp_async16(uint32_t dst, const void* src) {
    asm volatile("cp.async.cg.shared.global [%0], [%1], 16;"
                 :: "r"(dst), "l"(src) : "memory");
}
#define CP_COMMIT()  asm volatile("cp.async.commit_group;" ::: "memory")
#define CP_WAIT(n)   asm volatile("cp.async.wait_group %0;" :: "n"(n) : "memory")

__device__ __forceinline__ void ldsm_x4(uint32_t r[4], uint32_t addr) {
    asm volatile("ldmatrix.sync.aligned.m8n8.x4.shared.b16 {%0,%1,%2,%3}, [%4];"
                 : "=r"(r[0]), "=r"(r[1]), "=r"(r[2]), "=r"(r[3]) : "r"(addr));
}
__device__ __forceinline__ uint32_t cvt_tf32(uint32_t x) {
    uint32_t y;
    asm volatile("cvt.rna.tf32.f32 %0, %1;" : "=r"(y) : "r"(x));
    return y;
}
__device__ __forceinline__ void mma_tf32(float d[4], const uint32_t a[4],
                                         uint32_t b0, uint32_t b1) {
    asm volatile(
        "mma.sync.aligned.m16n8k8.row.col.f32.tf32.tf32.f32 "
        "{%0,%1,%2,%3}, {%4,%5,%6,%7}, {%8,%9}, {%0,%1,%2,%3};"
        : "+f"(d[0]), "+f"(d[1]), "+f"(d[2]), "+f"(d[3])
        : "r"(a[0]), "r"(a[1]), "r"(a[2]), "r"(a[3]), "r"(b0), "r"(b1));
}

__global__ __launch_bounds__(THREADS, 1)
void tf32_mma_gemm(const float* __restrict__ A,    // x [M,K]
                   const float* __restrict__ W,    // w [N,K]
                   const float* __restrict__ bias, // [N]
                   float* __restrict__ C)          // [M,N]
{
    extern __shared__ char smem[];
    const uint32_t sb = smem_u32(smem);

    const int tid  = threadIdx.x;
    const int lane = tid & 31;
    const int wid  = tid >> 5;
    const int warp_m = wid >> 2;   // 0..1  -> 64 rows
    const int warp_n = wid & 3;    // 0..3  -> 32 cols

    const int bm = blockIdx.y * BM;
    const int bn = blockIdx.x * BN;

    // ---- cp.async offsets: 4 x 16B chunks per thread per operand tile ----
    // tile = 128 rows x 128B = 1024 chunks; idx -> row=idx>>3, chunk c=idx&7
    uint32_t a_go[4], a_so[4], b_go[4], b_so[4];
    #pragma unroll
    for (int t = 0; t < 4; t++) {
        int idx = t * THREADS + tid;
        int r = idx >> 3, c = idx & 7;
        a_go[t] = (uint32_t)(r * (Kdim * 4) + c * 16);
        a_so[t] = sw128((uint32_t)(r * 128 + c * 16));
        b_go[t] = a_go[t];
        b_so[t] = a_so[t];
    }
    const char* Abase = (const char*)(A + (size_t)bm * Kdim);
    const char* Bbase = (const char*)(W + (size_t)bn * Kdim);

    auto load_tile = [&](int stage, int kt) {
        const uint32_t sA = sb + (uint32_t)stage * STAGE_BYTES;
        const uint32_t sB = sA + A_BYTES;
        const char* Ak = Abase + (uint32_t)kt * (BK * 4);
        const char* Bk = Bbase + (uint32_t)kt * (BK * 4);
        #pragma unroll
        for (int t = 0; t < 4; t++) cp_async16(sA + a_so[t], Ak + a_go[t]);
        #pragma unroll
        for (int t = 0; t < 4; t++) cp_async16(sB + b_so[t], Bk + b_go[t]);
    };

    // ---- ldmatrix per-lane base offsets ----
    // A x4 tiles: lanes0-7 rows0-7@k0, 8-15 rows8-15@k0, 16-23 rows0-7@k+16B,
    // 24-31 rows8-15@k+16B  -> regs = a0,a1,a2,a3 of m16n8k8 tf32 fragment.
    const int lr  = lane & 7;
    const int g1  = (lane >> 3) & 1;
    const int hi  = lane >> 4;
    const uint32_t a_boff = (uint32_t)((warp_m * 64 + g1 * 8 + lr) * 128 + hi * 16);
    // B x4 tiles over [n][k] storage: lanes0-7 n0-7@k0, 8-15 n0-7@k+16,
    // 16-23 n8-15@k0, 24-31 n8-15@k+16 -> regs = b0/b1 of ntile0, b0/b1 ntile1.
    const uint32_t b_boff = (uint32_t)((warp_n * 32 + hi * 8 + lr) * 128 + g1 * 16);

    float d[4][4][4];
    #pragma unroll
    for (int mi = 0; mi < 4; mi++)
        #pragma unroll
        for (int ni = 0; ni < 4; ni++)
            #pragma unroll
            for (int r = 0; r < 4; r++) d[mi][ni][r] = 0.0f;

    // ---- prologue ----
    #pragma unroll
    for (int p = 0; p < STAGES - 1; p++) { load_tile(p, p); CP_COMMIT(); }

    int cs = 0;   // compute stage
    for (int kt = 0; kt < KT; kt++) {
        CP_WAIT(STAGES - 2);
        __syncthreads();

        // prefetch stage (kt+S-1): buffer index (cs-1) mod S
        {
            int lkt = kt + STAGES - 1;
            int lst = cs - 1; if (lst < 0) lst += STAGES;
            if (lkt < KT) load_tile(lst, lkt);
            CP_COMMIT();
        }

        const uint32_t sA = sb + (uint32_t)cs * STAGE_BYTES;
        const uint32_t sB = sA + A_BYTES;

        #pragma unroll
        for (int ks = 0; ks < 4; ks++) {          // 4 x k=8 per 32-k tile
            uint32_t a[4][4];
            #pragma unroll
            for (int mi = 0; mi < 4; mi++) {
                ldsm_x4(a[mi], sA + sw128(a_boff + mi * 2048 + ks * 32));
                #pragma unroll
                for (int r = 0; r < 4; r++) a[mi][r] = cvt_tf32(a[mi][r]);
            }
            uint32_t b[2][4];
            #pragma unroll
            for (int ns = 0; ns < 2; ns++) {
                ldsm_x4(b[ns], sB + sw128(b_boff + ns * 2048 + ks * 32));
                #pragma unroll
                for (int r = 0; r < 4; r++) b[ns][r] = cvt_tf32(b[ns][r]);
            }
            #pragma unroll
            for (int mi = 0; mi < 4; mi++)
                #pragma unroll
                for (int ni = 0; ni < 4; ni++)
                    mma_tf32(d[mi][ni], a[mi],
                             b[ni >> 1][(ni & 1) * 2],
                             b[ni >> 1][(ni & 1) * 2 + 1]);
        }

        cs = (cs + 1 < STAGES) ? cs + 1 : 0;
    }

    // ---- epilogue: bias + stores (4 adjacent lanes cover one 32B sector) ----
    #pragma unroll
    for (int ni = 0; ni < 4; ni++) {
        const int col = bn + warp_n * 32 + ni * 8 + (lane & 3) * 2;
        const float2 bv = *(const float2*)(bias + col);
        #pragma unroll
        for (int mi = 0; mi < 4; mi++) {
            const int row0 = bm + warp_m * 64 + mi * 16 + (lane >> 2);
            float2 v0 = { d[mi][ni][0] + bv.x, d[mi][ni][1] + bv.y };
            float2 v1 = { d[mi][ni][2] + bv.x, d[mi][ni][3] + bv.y };
            *(float2*)(C + (size_t)row0 * Ndim + col) = v0;
            *(float2*)(C + (size_t)(row0 + 8) * Ndim + col) = v1;
        }
    }
}

} // namespace

extern "C" void kernel_launch(void* const* d_in, const int* in_sizes, int n_in,
                              void* d_out, int out_size)
{
    const float* x    = (const float*)d_in[0];
    const float* w    = (const float*)d_in[1];
    const float* bias = (const float*)d_in[2];
    float* out        = (float*)d_out;

    cudaFuncSetAttribute(tf32_mma_gemm,
                         cudaFuncAttributeMaxDynamicSharedMemorySize, SMEM_TOTAL);

    dim3 grid(Ndim / BN, Mdim / BM);   // (16, 32) = 512 CTAs
    tf32_mma_gemm<<<grid, THREADS, SMEM_TOTAL>>>(x, w, bias, out);
}

// round 4
// speedup vs baseline: 3.2113x; 1.0474x over previous
#include <cuda_runtime.h>
#include <cstdint>

// out[4096,2048] = x[4096,2048] @ W[2048,2048]^T + bias   (fp32 in/out)
// Two-phase: (1) pre-round x,W to tf32 (stored fp32) into device-global
// scratch; (2) tf32 mma.sync.m16n8k8 GEMM with NO cvt in the mainloop.
// 5-stage cp.async pipeline, SW128 swizzle, ldmatrix-b16 fragment loads.

namespace {

constexpr int Mdim = 4096;
constexpr int Ndim = 2048;
constexpr int Kdim = 2048;

constexpr int BM = 128;
constexpr int BN = 128;
constexpr int BK = 32;                    // 32 f32 = 128 B rows (SW128 atom)
constexpr int KT = Kdim / BK;             // 64 k-tiles
constexpr int STAGES = 5;

constexpr uint32_t A_BYTES = BM * BK * 4;
constexpr uint32_t B_BYTES = BN * BK * 4;
constexpr uint32_t STAGE_BYTES = A_BYTES + B_BYTES;   // 32768
constexpr uint32_t SMEM_TOTAL = STAGES * STAGE_BYTES; // 163840

constexpr int THREADS = 256;

// tf32-rounded copies of the inputs (BSS scratch; allowed per harness rules)
__device__ float g_xa[(size_t)Mdim * Kdim];   // 32 MB
__device__ float g_wb[(size_t)Ndim * Kdim];   // 16 MB

__device__ __forceinline__ uint32_t smem_u32(const void* p) {
    return (uint32_t)__cvta_generic_to_shared(p);
}
__device__ __forceinline__ uint32_t sw128(uint32_t off) {
    return off ^ ((off >> 3) & 0x70);
}
__device__ __forceinline__ void cp_async16(uint32_t dst, const void* src) {
    asm volatile("cp.async.cg.shared.global [%0], [%1], 16;"
                 :: "r"(dst), "l"(src) : "memory");
}
#define CP_COMMIT()  asm volatile("cp.async.commit_group;" ::: "memory")
#define CP_WAIT(n)   asm volatile("cp.async.wait_group %0;" :: "n"(n) : "memory")

__device__ __forceinline__ void ldsm_x4(uint32_t r[4], uint32_t addr) {
    asm volatile("ldmatrix.sync.aligned.m8n8.x4.shared.b16 {%0,%1,%2,%3}, [%4];"
                 : "=r"(r[0]), "=r"(r[1]), "=r"(r[2]), "=r"(r[3]) : "r"(addr));
}
__device__ __forceinline__ uint32_t cvt_tf32(uint32_t x) {
    uint32_t y;
    asm volatile("cvt.rna.tf32.f32 %0, %1;" : "=r"(y) : "r"(x));
    return y;
}
__device__ __forceinline__ void mma_tf32(float d[4], const uint32_t a[4],
                                         uint32_t b0, uint32_t b1) {
    asm volatile(
        "mma.sync.aligned.m16n8k8.row.col.f32.tf32.tf32.f32 "
        "{%0,%1,%2,%3}, {%4,%5,%6,%7}, {%8,%9}, {%0,%1,%2,%3};"
        : "+f"(d[0]), "+f"(d[1]), "+f"(d[2]), "+f"(d[3])
        : "r"(a[0]), "r"(a[1]), "r"(a[2]), "r"(a[3]), "r"(b0), "r"(b1));
}

// ---- phase 1: round to tf32 once, store as fp32 ----
__global__ __launch_bounds__(256)
void cvt_pass(const float4* __restrict__ sx, const float4* __restrict__ sw)
{
    constexpr int NX4 = Mdim * Kdim / 4;   // 2M
    constexpr int NW4 = Ndim * Kdim / 4;   // 1M
    float4* __restrict__ dx = (float4*)g_xa;
    float4* __restrict__ dw = (float4*)g_wb;

    const int stride = gridDim.x * blockDim.x;
    for (int i = blockIdx.x * blockDim.x + threadIdx.x; i < NX4; i += stride) {
        float4 v = sx[i];
        uint4 o;
        o.x = cvt_tf32(__float_as_uint(v.x));
        o.y = cvt_tf32(__float_as_uint(v.y));
        o.z = cvt_tf32(__float_as_uint(v.z));
        o.w = cvt_tf32(__float_as_uint(v.w));
        *(uint4*)&dx[i] = o;
    }
    for (int i = blockIdx.x * blockDim.x + threadIdx.x; i < NW4; i += stride) {
        float4 v = sw[i];
        uint4 o;
        o.x = cvt_tf32(__float_as_uint(v.x));
        o.y = cvt_tf32(__float_as_uint(v.y));
        o.z = cvt_tf32(__float_as_uint(v.z));
        o.w = cvt_tf32(__float_as_uint(v.w));
        *(uint4*)&dw[i] = o;
    }
}

// ---- phase 2: GEMM ----
__global__ __launch_bounds__(THREADS, 1)
void tf32_mma_gemm(const float* __restrict__ bias, float* __restrict__ C)
{
    extern __shared__ char smem[];
    const uint32_t sb = smem_u32(smem);

    const float* __restrict__ A = g_xa;
    const float* __restrict__ W = g_wb;

    const int tid  = threadIdx.x;
    const int lane = tid & 31;
    const int wid  = tid >> 5;
    const int warp_m = wid >> 2;   // 0..1  -> 64 rows
    const int warp_n = wid & 3;    // 0..3  -> 32 cols

    const int bm = blockIdx.y * BM;
    const int bn = blockIdx.x * BN;

    // cp.async offsets: 4 x 16B chunks per thread per operand tile
    uint32_t a_go[4], a_so[4];
    #pragma unroll
    for (int t = 0; t < 4; t++) {
        int idx = t * THREADS + tid;
        int r = idx >> 3, c = idx & 7;
        a_go[t] = (uint32_t)(r * (Kdim * 4) + c * 16);
        a_so[t] = sw128((uint32_t)(r * 128 + c * 16));
    }
    const char* Abase = (const char*)(A + (size_t)bm * Kdim);
    const char* Bbase = (const char*)(W + (size_t)bn * Kdim);

    auto load_tile = [&](int stage, int kt) {
        const uint32_t sA = sb + (uint32_t)stage * STAGE_BYTES;
        const uint32_t sB = sA + A_BYTES;
        const char* Ak = Abase + (uint32_t)kt * (BK * 4);
        const char* Bk = Bbase + (uint32_t)kt * (BK * 4);
        #pragma unroll
        for (int t = 0; t < 4; t++) cp_async16(sA + a_so[t], Ak + a_go[t]);
        #pragma unroll
        for (int t = 0; t < 4; t++) cp_async16(sB + a_so[t], Bk + a_go[t]);
    };

    // ldmatrix per-lane base offsets (same mapping as validated in R3)
    const int lr  = lane & 7;
    const int g1  = (lane >> 3) & 1;
    const int hi  = lane >> 4;
    const uint32_t a_boff = (uint32_t)((warp_m * 64 + g1 * 8 + lr) * 128 + hi * 16);
    const uint32_t b_boff = (uint32_t)((warp_n * 32 + hi * 8 + lr) * 128 + g1 * 16);

    float d[4][4][4];
    #pragma unroll
    for (int mi = 0; mi < 4; mi++)
        #pragma unroll
        for (int ni = 0; ni < 4; ni++)
            #pragma unroll
            for (int r = 0; r < 4; r++) d[mi][ni][r] = 0.0f;

    #pragma unroll
    for (int p = 0; p < STAGES - 1; p++) { load_tile(p, p); CP_COMMIT(); }

    int cs = 0;
    for (int kt = 0; kt < KT; kt++) {
        CP_WAIT(STAGES - 2);
        __syncthreads();

        {
            int lkt = kt + STAGES - 1;
            int lst = cs - 1; if (lst < 0) lst += STAGES;
            if (lkt < KT) load_tile(lst, lkt);
            CP_COMMIT();
        }

        const uint32_t sA = sb + (uint32_t)cs * STAGE_BYTES;
        const uint32_t sB = sA + A_BYTES;

        #pragma unroll
        for (int ks = 0; ks < 4; ks++) {          // 4 x k=8 per 32-k tile
            uint32_t a[4][4];
            #pragma unroll
            for (int mi = 0; mi < 4; mi++)
                ldsm_x4(a[mi], sA + sw128(a_boff + mi * 2048 + ks * 32));
            uint32_t b[2][4];
            #pragma unroll
            for (int ns = 0; ns < 2; ns++)
                ldsm_x4(b[ns], sB + sw128(b_boff + ns * 2048 + ks * 32));
            #pragma unroll
            for (int mi = 0; mi < 4; mi++)
                #pragma unroll
                for (int ni = 0; ni < 4; ni++)
                    mma_tf32(d[mi][ni], a[mi],
                             b[ni >> 1][(ni & 1) * 2],
                             b[ni >> 1][(ni & 1) * 2 + 1]);
        }

        cs = (cs + 1 < STAGES) ? cs + 1 : 0;
    }

    // epilogue: bias + float2 stores (4 adjacent lanes = one 32B sector)
    #pragma unroll
    for (int ni = 0; ni < 4; ni++) {
        const int col = bn + warp_n * 32 + ni * 8 + (lane & 3) * 2;
        const float2 bv = *(const float2*)(bias + col);
        #pragma unroll
        for (int mi = 0; mi < 4; mi++) {
            const int row0 = bm + warp_m * 64 + mi * 16 + (lane >> 2);
            float2 v0 = { d[mi][ni][0] + bv.x, d[mi][ni][1] + bv.y };
            float2 v1 = { d[mi][ni][2] + bv.x, d[mi][ni][3] + bv.y };
            *(float2*)(C + (size_t)row0 * Ndim + col) = v0;
            *(float2*)(C + (size_t)(row0 + 8) * Ndim + col) = v1;
        }
    }
}

} // namespace

extern "C" void kernel_launch(void* const* d_in, const int* in_sizes, int n_in,
                              void* d_out, int out_size)
{
    const float* x    = (const float*)d_in[0];
    const float* w    = (const float*)d_in[1];
    const float* bias = (const float*)d_in[2];
    float* out        = (float*)d_out;

    cudaFuncSetAttribute(tf32_mma_gemm,
                         cudaFuncAttributeMaxDynamicSharedMemorySize, SMEM_TOTAL);

    // Phase 1: one-time-per-call tf32 rounding of x and W into scratch.
    cvt_pass<<<2048, 256>>>((const float4*)x, (const float4*)w);

    // Phase 2: GEMM (reads scratch, writes out). Same stream -> ordered.
    dim3 grid(Ndim / BN, Mdim / BM);   // (16, 32) = 512 CTAs
    tf32_mma_gemm<<<grid, THREADS, SMEM_TOTAL>>>(bias, out);
}

// round 5
// speedup vs baseline: 3.8246x; 1.1910x over previous
#include <cuda_runtime.h>
#include <cstdint>

// out[4096,2048] = x[4096,2048] @ W[2048,2048]^T + bias   (fp32 in/out)
// Phase 1: pre-round x,W to tf32 (stored fp32) into device-global scratch.
// Phase 2: tf32 mma.sync.m16n8k8 GEMM, 3-stage cp.async pipeline, SW128
// swizzle, ldmatrix-b16 fragment loads, 2 CTAs/SM (96KB smem, <=128 regs).

namespace {

constexpr int Mdim = 4096;
constexpr int Ndim = 2048;
constexpr int Kdim = 2048;

constexpr int BM = 128;
constexpr int BN = 128;
constexpr int BK = 32;                    // 32 f32 = 128 B rows (SW128 atom)
constexpr int KT = Kdim / BK;             // 64 k-tiles
constexpr int STAGES = 3;

constexpr uint32_t A_BYTES = BM * BK * 4;
constexpr uint32_t B_BYTES = BN * BK * 4;
constexpr uint32_t STAGE_BYTES = A_BYTES + B_BYTES;   // 32768
constexpr uint32_t SMEM_TOTAL = STAGES * STAGE_BYTES; // 98304

constexpr int THREADS = 256;

// tf32-rounded copies of the inputs (BSS scratch; allowed per harness rules)
__device__ float g_xa[(size_t)Mdim * Kdim];   // 32 MB
__device__ float g_wb[(size_t)Ndim * Kdim];   // 16 MB

__device__ __forceinline__ uint32_t smem_u32(const void* p) {
    return (uint32_t)__cvta_generic_to_shared(p);
}
__device__ __forceinline__ uint32_t sw128(uint32_t off) {
    return off ^ ((off >> 3) & 0x70);
}
__device__ __forceinline__ void cp_async16(uint32_t dst, const void* src) {
    asm volatile("cp.async.cg.shared.global [%0], [%1], 16;"
                 :: "r"(dst), "l"(src) : "memory");
}
#define CP_COMMIT()  asm volatile("cp.async.commit_group;" ::: "memory")
#define CP_WAIT(n)   asm volatile("cp.async.wait_group %0;" :: "n"(n) : "memory")

__device__ __forceinline__ void ldsm_x4(uint32_t r[4], uint32_t addr) {
    asm volatile("ldmatrix.sync.aligned.m8n8.x4.shared.b16 {%0,%1,%2,%3}, [%4];"
                 : "=r"(r[0]), "=r"(r[1]), "=r"(r[2]), "=r"(r[3]) : "r"(addr));
}
__device__ __forceinline__ uint32_t cvt_tf32(uint32_t x) {
    uint32_t y;
    asm volatile("cvt.rna.tf32.f32 %0, %1;" : "=r"(y) : "r"(x));
    return y;
}
__device__ __forceinline__ void mma_tf32(float d[4], const uint32_t a[4],
                                         uint32_t b0, uint32_t b1) {
    asm volatile(
        "mma.sync.aligned.m16n8k8.row.col.f32.tf32.tf32.f32 "
        "{%0,%1,%2,%3}, {%4,%5,%6,%7}, {%8,%9}, {%0,%1,%2,%3};"
        : "+f"(d[0]), "+f"(d[1]), "+f"(d[2]), "+f"(d[3])
        : "r"(a[0]), "r"(a[1]), "r"(a[2]), "r"(a[3]), "r"(b0), "r"(b1));
}

// ---- phase 1: round to tf32 once, store as fp32 ----
__global__ __launch_bounds__(256)
void cvt_pass(const float4* __restrict__ sx, const float4* __restrict__ sw)
{
    constexpr int NX4 = Mdim * Kdim / 4;
    constexpr int NW4 = Ndim * Kdim / 4;
    float4* __restrict__ dx = (float4*)g_xa;
    float4* __restrict__ dw = (float4*)g_wb;

    const int stride = gridDim.x * blockDim.x;
    for (int i = blockIdx.x * blockDim.x + threadIdx.x; i < NX4; i += stride) {
        float4 v = sx[i];
        uint4 o;
        o.x = cvt_tf32(__float_as_uint(v.x));
        o.y = cvt_tf32(__float_as_uint(v.y));
        o.z = cvt_tf32(__float_as_uint(v.z));
        o.w = cvt_tf32(__float_as_uint(v.w));
        *(uint4*)&dx[i] = o;
    }
    for (int i = blockIdx.x * blockDim.x + threadIdx.x; i < NW4; i += stride) {
        float4 v = sw[i];
        uint4 o;
        o.x = cvt_tf32(__float_as_uint(v.x));
        o.y = cvt_tf32(__float_as_uint(v.y));
        o.z = cvt_tf32(__float_as_uint(v.z));
        o.w = cvt_tf32(__float_as_uint(v.w));
        *(uint4*)&dw[i] = o;
    }
}

// ---- phase 2: GEMM ----
__global__ __launch_bounds__(THREADS, 2)
void tf32_mma_gemm(const float* __restrict__ bias, float* __restrict__ C)
{
    extern __shared__ char smem[];
    const uint32_t sb = smem_u32(smem);

    const float* __restrict__ A = g_xa;
    const float* __restrict__ W = g_wb;

    const int tid  = threadIdx.x;
    const int lane = tid & 31;
    const int wid  = tid >> 5;
    const int warp_m = wid >> 2;   // 0..1  -> 64 rows
    const int warp_n = wid & 3;    // 0..3  -> 32 cols

    const int bm = blockIdx.y * BM;
    const int bn = blockIdx.x * BN;

    // cp.async offsets: 4 x 16B chunks per thread per operand tile
    uint32_t a_go[4], a_so[4];
    #pragma unroll
    for (int t = 0; t < 4; t++) {
        int idx = t * THREADS + tid;
        int r = idx >> 3, c = idx & 7;
        a_go[t] = (uint32_t)(r * (Kdim * 4) + c * 16);
        a_so[t] = sw128((uint32_t)(r * 128 + c * 16));
    }
    const char* Abase = (const char*)(A + (size_t)bm * Kdim);
    const char* Bbase = (const char*)(W + (size_t)bn * Kdim);

    auto load_tile = [&](int stage, int kt) {
        const uint32_t sA = sb + (uint32_t)stage * STAGE_BYTES;
        const uint32_t sB = sA + A_BYTES;
        const char* Ak = Abase + (uint32_t)kt * (BK * 4);
        const char* Bk = Bbase + (uint32_t)kt * (BK * 4);
        #pragma unroll
        for (int t = 0; t < 4; t++) cp_async16(sA + a_so[t], Ak + a_go[t]);
        #pragma unroll
        for (int t = 0; t < 4; t++) cp_async16(sB + a_so[t], Bk + a_go[t]);
    };

    // ldmatrix per-lane base offsets (mapping validated in R3/R4)
    const int lr  = lane & 7;
    const int g1  = (lane >> 3) & 1;
    const int hi  = lane >> 4;
    const uint32_t a_boff = (uint32_t)((warp_m * 64 + g1 * 8 + lr) * 128 + hi * 16);
    const uint32_t b_boff = (uint32_t)((warp_n * 32 + hi * 8 + lr) * 128 + g1 * 16);

    float d[4][4][4];
    #pragma unroll
    for (int mi = 0; mi < 4; mi++)
        #pragma unroll
        for (int ni = 0; ni < 4; ni++)
            #pragma unroll
            for (int r = 0; r < 4; r++) d[mi][ni][r] = 0.0f;

    #pragma unroll
    for (int p = 0; p < STAGES - 1; p++) { load_tile(p, p); CP_COMMIT(); }

    int cs = 0;
    for (int kt = 0; kt < KT; kt++) {
        CP_WAIT(STAGES - 2);
        __syncthreads();

        {
            int lkt = kt + STAGES - 1;
            int lst = cs - 1; if (lst < 0) lst += STAGES;
            if (lkt < KT) load_tile(lst, lkt);
            CP_COMMIT();
        }

        const uint32_t sA = sb + (uint32_t)cs * STAGE_BYTES;
        const uint32_t sB = sA + A_BYTES;

        #pragma unroll
        for (int ks = 0; ks < 4; ks++) {          // 4 x k=8 per 32-k tile
            uint32_t a[4][4];
            #pragma unroll
            for (int mi = 0; mi < 4; mi++)
                ldsm_x4(a[mi], sA + sw128(a_boff + mi * 2048 + ks * 32));
            uint32_t b[2][4];
            #pragma unroll
            for (int ns = 0; ns < 2; ns++)
                ldsm_x4(b[ns], sB + sw128(b_boff + ns * 2048 + ks * 32));
            #pragma unroll
            for (int mi = 0; mi < 4; mi++)
                #pragma unroll
                for (int ni = 0; ni < 4; ni++)
                    mma_tf32(d[mi][ni], a[mi],
                             b[ni >> 1][(ni & 1) * 2],
                             b[ni >> 1][(ni & 1) * 2 + 1]);
        }

        cs = (cs + 1 < STAGES) ? cs + 1 : 0;
    }

    // epilogue: bias + float2 stores (4 adjacent lanes = one 32B sector)
    #pragma unroll
    for (int ni = 0; ni < 4; ni++) {
        const int col = bn + warp_n * 32 + ni * 8 + (lane & 3) * 2;
        const float2 bv = *(const float2*)(bias + col);
        #pragma unroll
        for (int mi = 0; mi < 4; mi++) {
            const int row0 = bm + warp_m * 64 + mi * 16 + (lane >> 2);
            float2 v0 = { d[mi][ni][0] + bv.x, d[mi][ni][1] + bv.y };
            float2 v1 = { d[mi][ni][2] + bv.x, d[mi][ni][3] + bv.y };
            *(float2*)(C + (size_t)row0 * Ndim + col) = v0;
            *(float2*)(C + (size_t)(row0 + 8) * Ndim + col) = v1;
        }
    }
}

} // namespace

extern "C" void kernel_launch(void* const* d_in, const int* in_sizes, int n_in,
                              void* d_out, int out_size)
{
    const float* x    = (const float*)d_in[0];
    const float* w    = (const float*)d_in[1];
    const float* bias = (const float*)d_in[2];
    float* out        = (float*)d_out;

    cudaFuncSetAttribute(tf32_mma_gemm,
                         cudaFuncAttributeMaxDynamicSharedMemorySize, SMEM_TOTAL);

    // Phase 1: one-time-per-call tf32 rounding of x and W into scratch.
    cvt_pass<<<2048, 256>>>((const float4*)x, (const float4*)w);

    // Phase 2: GEMM (reads scratch, writes out). Same stream -> ordered.
    dim3 grid(Ndim / BN, Mdim / BM);   // (16, 32) = 512 CTAs
    tf32_mma_gemm<<<grid, THREADS, SMEM_TOTAL>>>(bias, out);
}